// round 16
// baseline (speedup 1.0000x reference)
#include <cuda_runtime.h>
#include <cuda_fp16.h>
#include <cuda_bf16.h>

#define NN      65536
#define NE      1048576
#define NG      64
#define NPG     1024
#define CF      8
#define RSTRIDE 64      // edge slots per node

typedef unsigned long long ull;

__device__ int   g_deg[NN];
__device__ int   g_cnt[NN];
__device__ int   g_cur[NN];
// interleave: [(node/8)][slot/2][node%8][slot%2] -> per sub-lane, slot pair = 16B
__device__ __align__(16) int2 g_edges[(size_t)NN * RSTRIDE];
__device__ __half g_tx[640ull * NN];          // Tx buffer in fp16 (GEMM A operand)
__device__ float g_ha[(size_t)NN * 64];
__device__ float g_hb[(size_t)NN * 64];
__device__ float g_hc[(size_t)NN * 128];      // K-split partials for layer 3

__device__ __forceinline__ ull pack2(float x, float y) {
    ull r; asm("mov.b64 %0, {%1, %2};" : "=l"(r) : "f"(x), "f"(y)); return r;
}
__device__ __forceinline__ void ffma2(ull& d, ull a, ull b) {
    asm("fma.rn.f32x2 %0, %1, %2, %0;" : "+l"(d) : "l"(a), "l"(b));
}
__device__ __forceinline__ void unpack2(ull v, float& x, float& y) {
    asm("mov.b64 {%0, %1}, %2;" : "=f"(x), "=f"(y) : "l"(v));
}
__device__ __forceinline__ void cp16(void* dst, const void* src) {
    unsigned int d = (unsigned int)__cvta_generic_to_shared(dst);
    asm volatile("cp.async.cg.shared.global [%0], [%1], 16;" :: "r"(d), "l"(src));
}

// ---------------- prep ----------------
// Tail-of-launch reset; __device__ arrays are zero at load, replays re-zero.
__global__ void zero_kernel() {
    int i = blockIdx.x * blockDim.x + threadIdx.x;
    if (i < NN) { g_deg[i] = 0; g_cnt[i] = 0; g_cur[i] = 0; }
}

__global__ void deg_kernel(const int* __restrict__ ei) {
    int e = blockIdx.x * blockDim.x + threadIdx.x;
    if (e >= NE) return;
    int s = ei[e], d = ei[NE + e];
    if (s != d) { atomicAdd(&g_deg[s], 1); atomicAdd(&g_cnt[d], 1); }
}

__global__ void fill_kernel(const int* __restrict__ ei,
                            const float* __restrict__ lam) {
    int e = blockIdx.x * blockDim.x + threadIdx.x;
    if (e >= NE) return;
    int s = ei[e], d = ei[NE + e];
    if (s == d) return;
    int od = g_deg[d];
    float dd = (od > 0) ? rsqrtf((float)od) : 0.0f;
    float w = -2.0f * rsqrtf((float)g_deg[s]) * dd / lam[s >> 10];
    int slot = atomicAdd(&g_cur[d], 1);
    int sloc = s & (NPG - 1);
    int eoff = (sloc << 5) | (((sloc >> 2) & 3) << 3);
    size_t idx = (size_t)(d & ~7) * RSTRIDE
               + (size_t)(slot >> 1) * 16 + (d & 7) * 2 + (slot & 1);
    g_edges[idx] = make_int2(eoff, __float_as_int(w));
}

// ---------------- Chebyshev recurrence (R11 core; fp16 writeout) ----------------
template<int F>
__global__ void __launch_bounds__(1024, 2)
spmv_kernel(const float* __restrict__ hin, const float* __restrict__ lam,
            __half* __restrict__ txout) {
    extern __shared__ float sm[];
    float* buf0 = sm;                   // [1024][8] swizzled
    float* buf1 = sm + NPG * 8;

    const int g = blockIdx.y, cb = blockIdx.x * CF, t = threadIdx.x;
    const int gbase = g * NPG;
    const float diag = 2.0f / lam[g] - 1.0f;

    const float* hp = hin + (size_t)gbase * F + cb;
    #pragma unroll
    for (int r = 0; r < CF; r++) {
        int i = r * 1024 + t;
        int row = i >> 3, f = i & 7;
        int sw = ((f >> 1) ^ ((row >> 2) & 3)) * 2 + (f & 1);
        buf0[row * 8 + sw] = hp[row * F + f];
    }
    __syncthreads();

    {
        int s_t = (t >> 2) & 3;
        #pragma unroll
        for (int f = 0; f < CF; f++) {
            int sw = ((f >> 1) ^ s_t) * 2 + (f & 1);
            txout[(size_t)(cb + f) * NN + gbase + t] = __float2half_rn(buf0[t * 8 + sw]);
        }
    }

    const int lane = t & 31, warp = t >> 5;
    const int fp8 = (lane & 3) * 8;
    const int sub = lane >> 2;
    int v = g_cnt[gbase + warp * 32 + lane];
    v = max(v, __shfl_xor_sync(0xffffffffu, v, 1));
    v = max(v, __shfl_xor_sync(0xffffffffu, v, 2));
    v = max(v, __shfl_xor_sync(0xffffffffu, v, 4));

    float* cur = buf0; float* oth = buf1;
    for (int k = 1; k < 5; k++) {
        const char* curb = (const char*)cur;
        #pragma unroll 1
        for (int p = 0; p < 4; p++) {
            const int gdeg = __shfl_sync(0xffffffffu, v, p * 8);
            const int node8 = warp * 32 + p * 8;
            const char* ebase =
                (const char*)(g_edges + (size_t)(gbase + node8) * RSTRIDE) + sub * 16;
            float ax = 0.0f, ay = 0.0f;
            #pragma unroll 1
            for (int i = 0; i < gdeg; i += 4) {
                int4 E0 = *(const int4*)(ebase + (size_t)i * 64);
                int4 E1 = *(const int4*)(ebase + (size_t)i * 64 + 128);
                float2 v0 = *(const float2*)(curb + (E0.x ^ fp8));
                float2 v1 = *(const float2*)(curb + (E0.z ^ fp8));
                float2 v2 = *(const float2*)(curb + (E1.x ^ fp8));
                float2 v3 = *(const float2*)(curb + (E1.z ^ fp8));
                float w0 = __int_as_float(E0.y), w1 = __int_as_float(E0.w);
                float w2 = __int_as_float(E1.y), w3 = __int_as_float(E1.w);
                ax = fmaf(w0, v0.x, ax); ay = fmaf(w0, v0.y, ay);
                ax = fmaf(w1, v1.x, ax); ay = fmaf(w1, v1.y, ay);
                ax = fmaf(w2, v2.x, ax); ay = fmaf(w2, v2.y, ay);
                ax = fmaf(w3, v3.x, ax); ay = fmaf(w3, v3.y, ay);
            }
            const int dloc = node8 + sub;
            const int swb = fp8 ^ (((dloc >> 2) & 3) << 3);
            float2 c = *(const float2*)((const char*)cur + dloc * 32 + swb);
            float lx = fmaf(diag, c.x, ax);
            float ly = fmaf(diag, c.y, ay);
            float2* op = (float2*)((char*)oth + dloc * 32 + swb);
            if (k > 1) { float2 o = *op; lx = 2.0f * lx - o.x; ly = 2.0f * ly - o.y; }
            *op = make_float2(lx, ly);
        }
        __syncthreads();
        int s_t = (t >> 2) & 3;
        #pragma unroll
        for (int f = 0; f < CF; f++) {
            int sw = ((f >> 1) ^ s_t) * 2 + (f & 1);
            txout[(size_t)(k * F + cb + f) * NN + gbase + t] =
                __float2half_rn(oth[t * 8 + sw]);
        }
        float* tmp = cur; cur = oth; oth = tmp;
        __syncthreads();
    }
}

// ---------------- GEMM v5: fp16 A, cp.async double buffer, optional K-split ----
// A:[K][NN] fp16, W:[K][N] fp32. SPLIT>1: each blockIdx.y writes raw partial to
// out + y*NN*N (no bias/relu); combine_kernel finishes.
template<int K, int N, int MT, int SPLIT>
__global__ void __launch_bounds__((MT / 8) * (N / 8))
gemm_kernel(const __half* __restrict__ A, const float* __restrict__ W,
            const float* __restrict__ bias, float* __restrict__ out) {
    constexpr int NJG = N / 8;
    constexpr int MG  = MT / 8;
    constexpr int T   = MG * NJG;
    constexpr int KS  = K / SPLIT;
    constexpr int S   = KS / 16;
    __shared__ __align__(16) __half As[2][16 * MT];
    __shared__ __align__(16) float  Ws[2][16 * N];

    const int t = threadIdx.x;
    const int jg = t % NJG, mg = t / NJG;
    const int m0 = blockIdx.x * MT;
    const int kbase = blockIdx.y * KS;

    auto prefetch = [&](int buf, int k0) {
        for (int i = t * 8; i < 16 * MT; i += T * 8)
            cp16(&As[buf][i], &A[(size_t)(kbase + k0 + i / MT) * NN + m0 + (i % MT)]);
        for (int i = t * 4; i < 16 * N; i += T * 4)
            cp16(&Ws[buf][i], &W[(size_t)(kbase + k0) * N + i]);
    };

    prefetch(0, 0);
    asm volatile("cp.async.commit_group;");

    ull acc[8][4];
    #pragma unroll
    for (int a = 0; a < 8; a++)
        #pragma unroll
        for (int b = 0; b < 4; b++) acc[a][b] = 0ULL;

    int buf = 0;
    for (int s = 0; s < S; s++) {
        if (s + 1 < S) prefetch(buf ^ 1, (s + 1) * 16);
        asm volatile("cp.async.commit_group;");
        asm volatile("cp.async.wait_group 1;");
        __syncthreads();
        #pragma unroll
        for (int kk = 0; kk < 16; kk++) {
            uint4 araw = *(const uint4*)&As[buf][kk * MT + mg * 8];
            float2 f0 = __half22float2(*(__half2*)&araw.x);
            float2 f1 = __half22float2(*(__half2*)&araw.y);
            float2 f2 = __half22float2(*(__half2*)&araw.z);
            float2 f3 = __half22float2(*(__half2*)&araw.w);
            const ull* wr = (const ull*)&Ws[buf][kk * N + jg * 8];
            ull w0 = wr[0], w1 = wr[1], w2 = wr[2], w3 = wr[3];
            float av[8] = {f0.x, f0.y, f1.x, f1.y, f2.x, f2.y, f3.x, f3.y};
            #pragma unroll
            for (int tt = 0; tt < 8; tt++) {
                ull ab = pack2(av[tt], av[tt]);
                ffma2(acc[tt][0], ab, w0);
                ffma2(acc[tt][1], ab, w1);
                ffma2(acc[tt][2], ab, w2);
                ffma2(acc[tt][3], ab, w3);
            }
        }
        __syncthreads();
        buf ^= 1;
    }

    float* po = (SPLIT > 1) ? out + (size_t)blockIdx.y * NN * N : out;
    #pragma unroll
    for (int tt = 0; tt < 8; tt++) {
        size_t node = m0 + mg * 8 + tt;
        #pragma unroll
        for (int p = 0; p < 4; p++) {
            float x, y; unpack2(acc[tt][p], x, y);
            int j = jg * 8 + 2 * p;
            if (SPLIT == 1) {
                x = fmaxf(x + bias[j], 0.0f);
                y = fmaxf(y + bias[j + 1], 0.0f);
            }
            *reinterpret_cast<float2*>(&po[node * N + j]) = make_float2(x, y);
        }
    }
}

// combine two K-split partials: o = relu(pa + pb + bias)
template<int NF>
__global__ void combine_kernel(const float* __restrict__ pa,
                               const float* __restrict__ pb,
                               const float* __restrict__ bias,
                               float* __restrict__ o) {
    size_t i = ((size_t)blockIdx.x * blockDim.x + threadIdx.x) * 4;
    float4 a = *(const float4*)(pa + i);
    float4 b = *(const float4*)(pb + i);
    float4 bb = *(const float4*)(bias + (int)(i % NF));
    float4 r;
    r.x = fmaxf(a.x + b.x + bb.x, 0.0f);
    r.y = fmaxf(a.y + b.y + bb.y, 0.0f);
    r.z = fmaxf(a.z + b.z + bb.z, 0.0f);
    r.w = fmaxf(a.w + b.w + bb.w, 0.0f);
    *(float4*)(o + i) = r;
}

// ---------------- pool + FC ----------------
__global__ void pool_fc_kernel(const float* __restrict__ h,
                               const float* __restrict__ fcW1, const float* __restrict__ fcb1,
                               const float* __restrict__ fcW2, const float* __restrict__ fcb2,
                               float* __restrict__ out) {
    __shared__ float red[256];
    __shared__ float pool[64];
    __shared__ float z1[10];
    int g = blockIdx.x, t = threadIdx.x;
    int f = t & 63, part = t >> 6;
    float s = 0.0f;
    for (int n = part; n < NPG; n += 4)
        s += h[(size_t)(g * NPG + n) * 64 + f];
    red[t] = s;
    __syncthreads();
    if (part == 0)
        pool[f] = (red[f] + red[64 + f] + red[128 + f] + red[192 + f]) * (1.0f / NPG);
    __syncthreads();
    if (t < 10) {
        float z = fcb1[t];
        for (int i = 0; i < 64; i++) z += pool[i] * fcW1[i * 10 + t];
        z1[t] = fmaxf(z, 0.0f);
    }
    __syncthreads();
    if (t < 10) {
        float z = fcb2[t];
        for (int j = 0; j < 10; j++) z += z1[j] * fcW2[j * 10 + t];
        out[g * 10 + t] = z;
    }
}

// ---------------- launch ----------------
extern "C" void kernel_launch(void* const* d_in, const int* in_sizes, int n_in,
                              void* d_out, int out_size) {
    const float* x     = (const float*)d_in[0];
    const int*   ei    = (const int*)d_in[1];
    const float* lam   = (const float*)d_in[3];
    const float* W1 = (const float*)d_in[4];  const float* b1 = (const float*)d_in[5];
    const float* W2 = (const float*)d_in[6];  const float* b2 = (const float*)d_in[7];
    const float* W3 = (const float*)d_in[8];  const float* b3 = (const float*)d_in[9];
    const float* fcW1 = (const float*)d_in[10]; const float* fcb1 = (const float*)d_in[11];
    const float* fcW2 = (const float*)d_in[12]; const float* fcb2 = (const float*)d_in[13];
    float* out = (float*)d_out;

    const int SMEM = 2 * NPG * CF * sizeof(float);  // 65536
    cudaFuncSetAttribute(spmv_kernel<128>, cudaFuncAttributeMaxDynamicSharedMemorySize, SMEM);
    cudaFuncSetAttribute(spmv_kernel<32>,  cudaFuncAttributeMaxDynamicSharedMemorySize, SMEM);
    cudaFuncSetAttribute(spmv_kernel<64>,  cudaFuncAttributeMaxDynamicSharedMemorySize, SMEM);

    __half* tx = nullptr; float* ha = nullptr; float* hb = nullptr; float* hc = nullptr;
    cudaGetSymbolAddress((void**)&tx, g_tx);
    cudaGetSymbolAddress((void**)&ha, g_ha);
    cudaGetSymbolAddress((void**)&hb, g_hb);
    cudaGetSymbolAddress((void**)&hc, g_hc);

    deg_kernel<<<NE / 256, 256>>>(ei);                      // 0
    fill_kernel<<<NE / 256, 256>>>(ei, lam);                // 1

    // ---- layer 1: K=640, N=32, split 2 ----
    spmv_kernel<128><<<dim3(16, NG), 1024, SMEM>>>(x, lam, tx);              // 2
    gemm_kernel<640, 32, 256, 2><<<dim3(NN / 256, 2), 128>>>(tx, W1, b1, hb); // 3 <- ncu
    combine_kernel<32><<<NN * 32 / 4 / 256, 256>>>(hb, hb + (size_t)NN * 32, b1, ha);

    // ---- layer 2: K=160, N=64, no split ----
    spmv_kernel<32><<<dim3(4, NG), 1024, SMEM>>>(ha, lam, tx);
    gemm_kernel<160, 64, 256, 1><<<dim3(NN / 256, 1), 256>>>(tx, W2, b2, hb);

    // ---- layer 3: K=320, N=64, split 2 ----
    spmv_kernel<64><<<dim3(8, NG), 1024, SMEM>>>(hb, lam, tx);
    gemm_kernel<320, 64, 256, 2><<<dim3(NN / 256, 2), 256>>>(tx, W3, b3, hc);
    combine_kernel<64><<<NN * 64 / 4 / 256, 256>>>(hc, hc + (size_t)NN * 64, b3, ha);

    pool_fc_kernel<<<NG, 256>>>(ha, fcW1, fcb1, fcW2, fcb2, out);

    zero_kernel<<<NN / 256, 256>>>();   // tail: reset counters for next replay
}

// round 17
// speedup vs baseline: 1.4122x; 1.4122x over previous
#include <cuda_runtime.h>
#include <cuda_fp16.h>
#include <cuda_bf16.h>

#define NN      65536
#define NE      1048576
#define NG      64
#define NPG     1024
#define CF      16      // features per chunk (fp16, 32B rows)
#define RSTRIDE 64      // edge slots per node

typedef unsigned long long ull;

__device__ int   g_deg[NN];
__device__ int   g_cnt[NN];
__device__ int   g_cur[NN];
// interleave: [(node/8)][slot/2][node%8][slot%2] -> per sub-lane, slot pair = 16B
__device__ __align__(16) int2 g_edges[(size_t)NN * RSTRIDE];
__device__ __half g_tx[640ull * NN];          // Tx buffer fp16 (GEMM A operand)
__device__ float g_ha[(size_t)NN * 64];
__device__ float g_hb[(size_t)NN * 64];

__device__ __forceinline__ ull pack2(float x, float y) {
    ull r; asm("mov.b64 %0, {%1, %2};" : "=l"(r) : "f"(x), "f"(y)); return r;
}
__device__ __forceinline__ void ffma2(ull& d, ull a, ull b) {
    asm("fma.rn.f32x2 %0, %1, %2, %0;" : "+l"(d) : "l"(a), "l"(b));
}
__device__ __forceinline__ void unpack2(ull v, float& x, float& y) {
    asm("mov.b64 {%0, %1}, %2;" : "=f"(x), "=f"(y) : "l"(v));
}
__device__ __forceinline__ void cp16(void* dst, const void* src) {
    unsigned int d = (unsigned int)__cvta_generic_to_shared(dst);
    asm volatile("cp.async.cg.shared.global [%0], [%1], 16;" :: "r"(d), "l"(src));
}

// ---------------- prep ----------------
__global__ void zero_kernel() {
    int i = blockIdx.x * blockDim.x + threadIdx.x;
    if (i < NN) { g_deg[i] = 0; g_cnt[i] = 0; g_cur[i] = 0; }
}

__global__ void deg_kernel(const int* __restrict__ ei) {
    int e = blockIdx.x * blockDim.x + threadIdx.x;
    if (e >= NE) return;
    int s = ei[e], d = ei[NE + e];
    if (s != d) { atomicAdd(&g_deg[s], 1); atomicAdd(&g_cnt[d], 1); }
}

__global__ void fill_kernel(const int* __restrict__ ei,
                            const float* __restrict__ lam) {
    int e = blockIdx.x * blockDim.x + threadIdx.x;
    if (e >= NE) return;
    int s = ei[e], d = ei[NE + e];
    if (s == d) return;
    int od = g_deg[d];
    float dd = (od > 0) ? rsqrtf((float)od) : 0.0f;
    float w = -2.0f * rsqrtf((float)g_deg[s]) * dd / lam[s >> 10];
    int slot = atomicAdd(&g_cur[d], 1);
    int sloc = s & (NPG - 1);
    // 32B-row byte offset with swizzle class baked in (bits 3-4)
    int eoff = (sloc << 5) | (((sloc >> 2) & 3) << 3);
    size_t idx = (size_t)(d & ~7) * RSTRIDE
               + (size_t)(slot >> 1) * 16 + (d & 7) * 2 + (slot & 1);
    g_edges[idx] = make_int2(eoff, __float_as_int(w));
}

// ---------------- Chebyshev recurrence: fp16 smem, 16 features / 32B row ----------------
// CTA = (16-feature chunk, graph), 1024 threads, 2 CTAs/SM (64KB smem).
// Warp iter: 8 nodes (sub=lane>>2); lane covers 4 features (granule fp=lane&3, 8B).
// fp32 accumulation in registers; fp16 only at smem load/store boundaries.
template<int F>
__global__ void __launch_bounds__(1024, 2)
spmv_kernel(const float* __restrict__ hin, const float* __restrict__ lam,
            __half* __restrict__ txout) {
    extern __shared__ __half smh[];
    __half* buf0 = smh;                 // [1024][16] fp16 swizzled
    __half* buf1 = smh + NPG * 16;

    const int g = blockIdx.y, cb = blockIdx.x * CF, t = threadIdx.x;
    const int gbase = g * NPG;
    const float diag = 2.0f / lam[g] - 1.0f;

    // load chunk: fp32 -> fp16 swizzled smem (granule g of row r at g^((r>>2)&3))
    const float* hp = hin + (size_t)gbase * F + cb;
    #pragma unroll
    for (int r = 0; r < CF; r++) {
        int i = r * 1024 + t;
        int row = i >> 4, f = i & 15;
        int sw = (((f >> 2) ^ ((row >> 2) & 3)) << 2) | (f & 3);
        buf0[row * 16 + sw] = __float2half_rn(hp[row * F + f]);
    }
    __syncthreads();

    // Tx0 -> transposed global (fp16 copy)
    {
        int s_t = (t >> 2) & 3;
        #pragma unroll
        for (int f = 0; f < CF; f++) {
            int sw = (((f >> 2) ^ s_t) << 2) | (f & 3);
            txout[(size_t)(cb + f) * NN + gbase + t] = buf0[t * 16 + sw];
        }
    }

    const int lane = t & 31, warp = t >> 5;
    const int fp8 = (lane & 3) * 8;
    const int sub = lane >> 2;
    int v = g_cnt[gbase + warp * 32 + lane];
    v = max(v, __shfl_xor_sync(0xffffffffu, v, 1));
    v = max(v, __shfl_xor_sync(0xffffffffu, v, 2));
    v = max(v, __shfl_xor_sync(0xffffffffu, v, 4));   // max deg per 8-node group

    __half* cur = buf0; __half* oth = buf1;
    for (int k = 1; k < 5; k++) {
        const char* curb = (const char*)cur;
        #pragma unroll 1
        for (int p = 0; p < 4; p++) {
            const int gdeg = __shfl_sync(0xffffffffu, v, p * 8);
            const int node8 = warp * 32 + p * 8;
            const char* ebase =
                (const char*)(g_edges + (size_t)(gbase + node8) * RSTRIDE) + sub * 16;
            float a0 = 0.0f, a1 = 0.0f, a2 = 0.0f, a3 = 0.0f;
            #pragma unroll 1
            for (int i = 0; i < gdeg; i += 4) {
                int4 E0 = *(const int4*)(ebase + (size_t)i * 64);
                int4 E1 = *(const int4*)(ebase + (size_t)i * 64 + 128);
                #pragma unroll
                for (int q = 0; q < 4; q++) {
                    int off = (q == 0) ? E0.x : (q == 1) ? E0.z : (q == 2) ? E1.x : E1.z;
                    int wb  = (q == 0) ? E0.y : (q == 1) ? E0.w : (q == 2) ? E1.y : E1.w;
                    uint2 hv = *(const uint2*)(curb + (off ^ fp8));
                    float2 g0 = __half22float2(*(const __half2*)&hv.x);
                    float2 g1 = __half22float2(*(const __half2*)&hv.y);
                    float w = __int_as_float(wb);
                    a0 = fmaf(w, g0.x, a0); a1 = fmaf(w, g0.y, a1);
                    a2 = fmaf(w, g1.x, a2); a3 = fmaf(w, g1.y, a3);
                }
            }
            const int dloc = node8 + sub;
            const int swb = fp8 ^ (((dloc >> 2) & 3) << 3);
            uint2 cown = *(const uint2*)((const char*)cur + dloc * 32 + swb);
            float2 c0 = __half22float2(*(const __half2*)&cown.x);
            float2 c1 = __half22float2(*(const __half2*)&cown.y);
            float l0 = fmaf(diag, c0.x, a0);
            float l1 = fmaf(diag, c0.y, a1);
            float l2 = fmaf(diag, c1.x, a2);
            float l3 = fmaf(diag, c1.y, a3);
            char* op = (char*)oth + dloc * 32 + swb;
            if (k > 1) {
                uint2 oo = *(const uint2*)op;
                float2 o0 = __half22float2(*(const __half2*)&oo.x);
                float2 o1 = __half22float2(*(const __half2*)&oo.y);
                l0 = 2.0f * l0 - o0.x;
                l1 = 2.0f * l1 - o0.y;
                l2 = 2.0f * l2 - o1.x;
                l3 = 2.0f * l3 - o1.y;
            }
            uint2 res;
            *(__half2*)&res.x = __floats2half2_rn(l0, l1);
            *(__half2*)&res.y = __floats2half2_rn(l2, l3);
            *(uint2*)op = res;
        }
        __syncthreads();
        int s_t = (t >> 2) & 3;
        #pragma unroll
        for (int f = 0; f < CF; f++) {
            int sw = (((f >> 2) ^ s_t) << 2) | (f & 3);
            txout[(size_t)(k * F + cb + f) * NN + gbase + t] = oth[t * 16 + sw];
        }
        __half* tmp = cur; cur = oth; oth = tmp;
        __syncthreads();
    }
}

// ---------------- GEMM: fp16 A, cp.async double buffering (no split) ----------------
// out = relu(A^T W + b); A:[K][NN] fp16, W:[K][N] fp32. threads = (MT/8)*(N/8).
template<int K, int N, int MT>
__global__ void __launch_bounds__((MT / 8) * (N / 8))
gemm_kernel(const __half* __restrict__ A, const float* __restrict__ W,
            const float* __restrict__ bias, float* __restrict__ out) {
    constexpr int NJG = N / 8;
    constexpr int MG  = MT / 8;
    constexpr int T   = MG * NJG;
    constexpr int S   = K / 16;
    __shared__ __align__(16) __half As[2][16 * MT];
    __shared__ __align__(16) float  Ws[2][16 * N];

    const int t = threadIdx.x;
    const int jg = t % NJG, mg = t / NJG;
    const int m0 = blockIdx.x * MT;

    auto prefetch = [&](int buf, int k0) {
        for (int i = t * 8; i < 16 * MT; i += T * 8)
            cp16(&As[buf][i], &A[(size_t)(k0 + i / MT) * NN + m0 + (i % MT)]);
        for (int i = t * 4; i < 16 * N; i += T * 4)
            cp16(&Ws[buf][i], &W[(size_t)k0 * N + i]);
    };

    prefetch(0, 0);
    asm volatile("cp.async.commit_group;");

    ull acc[8][4];
    #pragma unroll
    for (int a = 0; a < 8; a++)
        #pragma unroll
        for (int b = 0; b < 4; b++) acc[a][b] = 0ULL;

    int buf = 0;
    for (int s = 0; s < S; s++) {
        if (s + 1 < S) prefetch(buf ^ 1, (s + 1) * 16);
        asm volatile("cp.async.commit_group;");
        asm volatile("cp.async.wait_group 1;");
        __syncthreads();
        #pragma unroll
        for (int kk = 0; kk < 16; kk++) {
            uint4 araw = *(const uint4*)&As[buf][kk * MT + mg * 8];
            float2 f0 = __half22float2(*(__half2*)&araw.x);
            float2 f1 = __half22float2(*(__half2*)&araw.y);
            float2 f2 = __half22float2(*(__half2*)&araw.z);
            float2 f3 = __half22float2(*(__half2*)&araw.w);
            const ull* wr = (const ull*)&Ws[buf][kk * N + jg * 8];
            ull w0 = wr[0], w1 = wr[1], w2 = wr[2], w3 = wr[3];
            float av[8] = {f0.x, f0.y, f1.x, f1.y, f2.x, f2.y, f3.x, f3.y};
            #pragma unroll
            for (int tt = 0; tt < 8; tt++) {
                ull ab = pack2(av[tt], av[tt]);
                ffma2(acc[tt][0], ab, w0);
                ffma2(acc[tt][1], ab, w1);
                ffma2(acc[tt][2], ab, w2);
                ffma2(acc[tt][3], ab, w3);
            }
        }
        __syncthreads();
        buf ^= 1;
    }

    #pragma unroll
    for (int tt = 0; tt < 8; tt++) {
        size_t node = m0 + mg * 8 + tt;
        #pragma unroll
        for (int p = 0; p < 4; p++) {
            float x, y; unpack2(acc[tt][p], x, y);
            int j = jg * 8 + 2 * p;
            x = fmaxf(x + bias[j], 0.0f);
            y = fmaxf(y + bias[j + 1], 0.0f);
            *reinterpret_cast<float2*>(&out[node * N + j]) = make_float2(x, y);
        }
    }
}

// ---------------- pool + FC ----------------
__global__ void pool_fc_kernel(const float* __restrict__ h,
                               const float* __restrict__ fcW1, const float* __restrict__ fcb1,
                               const float* __restrict__ fcW2, const float* __restrict__ fcb2,
                               float* __restrict__ out) {
    __shared__ float red[256];
    __shared__ float pool[64];
    __shared__ float z1[10];
    int g = blockIdx.x, t = threadIdx.x;
    int f = t & 63, part = t >> 6;
    float s = 0.0f;
    for (int n = part; n < NPG; n += 4)
        s += h[(size_t)(g * NPG + n) * 64 + f];
    red[t] = s;
    __syncthreads();
    if (part == 0)
        pool[f] = (red[f] + red[64 + f] + red[128 + f] + red[192 + f]) * (1.0f / NPG);
    __syncthreads();
    if (t < 10) {
        float z = fcb1[t];
        for (int i = 0; i < 64; i++) z += pool[i] * fcW1[i * 10 + t];
        z1[t] = fmaxf(z, 0.0f);
    }
    __syncthreads();
    if (t < 10) {
        float z = fcb2[t];
        for (int j = 0; j < 10; j++) z += z1[j] * fcW2[j * 10 + t];
        out[g * 10 + t] = z;
    }
}

// ---------------- launch ----------------
extern "C" void kernel_launch(void* const* d_in, const int* in_sizes, int n_in,
                              void* d_out, int out_size) {
    const float* x     = (const float*)d_in[0];
    const int*   ei    = (const int*)d_in[1];
    const float* lam   = (const float*)d_in[3];
    const float* W1 = (const float*)d_in[4];  const float* b1 = (const float*)d_in[5];
    const float* W2 = (const float*)d_in[6];  const float* b2 = (const float*)d_in[7];
    const float* W3 = (const float*)d_in[8];  const float* b3 = (const float*)d_in[9];
    const float* fcW1 = (const float*)d_in[10]; const float* fcb1 = (const float*)d_in[11];
    const float* fcW2 = (const float*)d_in[12]; const float* fcb2 = (const float*)d_in[13];
    float* out = (float*)d_out;

    const int SMEM = 2 * NPG * CF * sizeof(__half);  // 65536
    cudaFuncSetAttribute(spmv_kernel<128>, cudaFuncAttributeMaxDynamicSharedMemorySize, SMEM);
    cudaFuncSetAttribute(spmv_kernel<32>,  cudaFuncAttributeMaxDynamicSharedMemorySize, SMEM);
    cudaFuncSetAttribute(spmv_kernel<64>,  cudaFuncAttributeMaxDynamicSharedMemorySize, SMEM);

    __half* tx = nullptr; float* ha = nullptr; float* hb = nullptr;
    cudaGetSymbolAddress((void**)&tx, g_tx);
    cudaGetSymbolAddress((void**)&ha, g_ha);
    cudaGetSymbolAddress((void**)&hb, g_hb);

    zero_kernel<<<NN / 256, 256>>>();                       // 0
    deg_kernel<<<NE / 256, 256>>>(ei);                      // 1
    fill_kernel<<<NE / 256, 256>>>(ei, lam);                // 2

    spmv_kernel<128><<<dim3(8, NG), 1024, SMEM>>>(x, lam, tx);      // 3 <- ncu
    gemm_kernel<640, 32, 256><<<NN / 256, 128>>>(tx, W1, b1, ha);

    spmv_kernel<32><<<dim3(2, NG), 1024, SMEM>>>(ha, lam, tx);
    gemm_kernel<160, 64, 256><<<NN / 256, 256>>>(tx, W2, b2, hb);

    spmv_kernel<64><<<dim3(4, NG), 1024, SMEM>>>(hb, lam, tx);
    gemm_kernel<320, 64, 256><<<NN / 256, 256>>>(tx, W3, b3, ha);

    pool_fc_kernel<<<NG, 256>>>(ha, fcW1, fcb1, fcW2, fcb2, out);
}